// round 14
// baseline (speedup 1.0000x reference)
#include <cuda_runtime.h>
#include <cuda_fp16.h>
#include <math.h>
#include <stdint.h>

// ---------------- problem constants ----------------
#define M_TOT 8192
#define KD    1024
#define ND    1024
#define EPSF  1.1920929e-07f
#define LAM_INIT 0.2f
#define ONE_MINUS_LAM_INIT 0.8f
#define SCALE_ATT 0.044194173824159216f

// ---------------- GEMM tiling: 128x64 tile, KC=32, 4 CTAs/SM ----------------
#define TILE_M 128
#define TILE_N 64
#define KC     32                  // K per stage
#define NIT    (KD/KC)             // 32
#define RS     40                  // smem row stride in halves (32 + 8 pad) = 80B
#define ST_A   (128*RS*2)          // 10240 B
#define ST_B   (64*RS*2)           // 5120 B
#define STG    (ST_A + ST_B)       // 15360 B per stage
#define SMEM_DYN (3*STG)           // 46080 -> 4 CTAs/SM (184KB smem, 64 regs)

#define WMAT   ((size_t)1048576)   // elems per weight matrix

// ---------------- scratch (__device__ globals; no allocs allowed) ----------------
__device__ float g_Q [(size_t)M_TOT * ND];
__device__ float g_K [(size_t)M_TOT * ND];
__device__ float g_V [(size_t)M_TOT * ND];
__device__ float g_y [(size_t)M_TOT * ND];     // rmsnorm3 + residual (fp32)
__device__ __align__(128) __half g_A1[(size_t)M_TOT * KD];   // 16MB fp16 activations
__device__ __align__(128) __half g_A2[(size_t)M_TOT * KD];   // 16MB fp16 h
__device__ __align__(128) __half g_W [5 * WMAT];             // 10MB: Wq|Wk|Wv|Wf1|Wf2

// ---------------- PTX helpers (base ISA only) ----------------
__device__ __forceinline__ uint32_t smem_u32(const void* p) {
    uint32_t a;
    asm("{ .reg .u64 t; cvta.to.shared.u64 t, %1; cvt.u32.u64 %0, t; }" : "=r"(a) : "l"(p));
    return a;
}
#define CP_ASYNC16(dst, src) \
    asm volatile("cp.async.cg.shared.global [%0], [%1], 16;" :: "r"(dst), "l"(src) : "memory")
#define CP_COMMIT() asm volatile("cp.async.commit_group;" ::: "memory")
#define CP_WAIT1()  asm volatile("cp.async.wait_group 1;" ::: "memory")

__device__ __forceinline__ void ldm_x4(uint32_t& r0, uint32_t& r1, uint32_t& r2, uint32_t& r3,
                                       uint32_t addr) {
    asm volatile("ldmatrix.sync.aligned.m8n8.x4.shared.b16 {%0,%1,%2,%3}, [%4];"
                 : "=r"(r0), "=r"(r1), "=r"(r2), "=r"(r3) : "r"(addr));
}
__device__ __forceinline__ void mma16816(float& c0, float& c1, float& c2, float& c3,
                                         uint32_t a0, uint32_t a1, uint32_t a2, uint32_t a3,
                                         uint32_t b0, uint32_t b1) {
    asm volatile("mma.sync.aligned.m16n8k16.row.col.f32.f16.f16.f32 "
                 "{%0,%1,%2,%3}, {%4,%5,%6,%7}, {%8,%9}, {%0,%1,%2,%3};"
                 : "+f"(c0), "+f"(c1), "+f"(c2), "+f"(c3)
                 : "r"(a0), "r"(a1), "r"(a2), "r"(a3), "r"(b0), "r"(b1));
}

__device__ __forceinline__ void half_store(__half* base, size_t row, int col,
                                           float vx, float vy) {
    __half2 hh; hh.x = __float2half_rn(vx); hh.y = __float2half_rn(vy);
    *(__half2*)&base[row * KD + col] = hh;
}

__device__ __forceinline__ float gelu_exact(float v) {
    return 0.5f * v * (1.0f + erff(v * 0.70710678118654752f));
}

// ---------------- prep: rmsnorm (blocks 0..8191) + weight convert (blocks 8192..9471) ----------------
__global__ void prep_k(const float* __restrict__ x, const float* __restrict__ g1,
                       __half* __restrict__ yh,
                       const float* __restrict__ w0, const float* __restrict__ w1,
                       const float* __restrict__ w2, const float* __restrict__ w3,
                       const float* __restrict__ w4, __half* __restrict__ Wall)
{
    const int tid = threadIdx.x;                   // 256
    if (blockIdx.x < M_TOT) {
        int row = blockIdx.x;
        const float4* xr = (const float4*)(x + (size_t)row * 1024);
        float4 v = xr[tid];
        float ss = v.x*v.x + v.y*v.y + v.z*v.z + v.w*v.w;
        #pragma unroll
        for (int o = 16; o > 0; o >>= 1) ss += __shfl_xor_sync(0xffffffffu, ss, o);
        __shared__ float sp[8];
        __shared__ float sscale;
        if ((tid & 31) == 0) sp[tid >> 5] = ss;
        __syncthreads();
        if (tid == 0) {
            float s = 0.f;
            #pragma unroll
            for (int i = 0; i < 8; i++) s += sp[i];
            sscale = rsqrtf(s * (1.0f/1024.0f) + EPSF);
        }
        __syncthreads();
        float sc = sscale;
        float4 wv = ((const float4*)g1)[tid];
        half_store(yh, (size_t)row, tid * 4,     v.x * sc * wv.x, v.y * sc * wv.y);
        half_store(yh, (size_t)row, tid * 4 + 2, v.z * sc * wv.z, v.w * sc * wv.w);
    } else {
        size_t b = (size_t)(blockIdx.x - M_TOT);   // 0..1279
        #pragma unroll
        for (int r = 0; r < 4; r++) {
            size_t i4 = b * 1024 + (size_t)r * 256 + tid;
            int m = (int)(i4 >> 18);
            const float* src = (m == 0) ? w0 : (m == 1) ? w1 : (m == 2) ? w2
                              : (m == 3) ? w3 : w4;
            float4 v = ((const float4*)src)[i4 & 262143];
            __half2 a; a.x = __float2half_rn(v.x); a.y = __float2half_rn(v.y);
            __half2 c; c.x = __float2half_rn(v.z); c.y = __float2half_rn(v.w);
            uint2 o; o.x = *(uint32_t*)&a; o.y = *(uint32_t*)&c;
            ((uint2*)Wall)[i4] = o;
        }
    }
}

// ---------------- stage loader: 128 A rows + 64 B rows, KC=32 (4 x 16B per row) ----------------
__device__ __forceinline__ void load_stage(uint32_t stage, const __half* Ab,
                                           const __half* Bb, int kiter, int tid)
{
    const int k0 = kiter * KC;
    // A: 512 chunks, B: 256 chunks; 3 per thread
    #pragma unroll
    for (int i = 0; i < 3; i++) {
        int idx = tid + i * 256;
        if (i < 2) {
            int r = idx >> 2, c = idx & 3;
            CP_ASYNC16(stage + (uint32_t)(r * (RS*2) + c * 16),
                       Ab + (size_t)r * KD + k0 + c * 8);
        } else {
            int j = idx - 512;                     // 0..255
            int r = j >> 2, c = j & 3;             // r 0..63
            CP_ASYNC16(stage + ST_A + (uint32_t)(r * (RS*2) + c * 16),
                       Bb + (size_t)r * KD + k0 + c * 8);
        }
    }
}

// ---------------- shared GEMM mainloop, fully unrolled (32x32 warp tiles) ----------------
__device__ __forceinline__ void gemm_mainloop(uint32_t sb, const __half* Abase,
                                              const __half* Bbase, int tid,
                                              const uint32_t* aoff, const uint32_t* boff,
                                              float acc[8][4])
{
    load_stage(sb,       Abase, Bbase, 0, tid); CP_COMMIT();
    load_stage(sb + STG, Abase, Bbase, 1, tid); CP_COMMIT();

    #pragma unroll
    for (int it = 0; it < NIT; it++) {
        const int slot  = it % 3;            // compile-time after unroll
        const int slot2 = (it + 2) % 3;
        CP_WAIT1();
        __syncthreads();
        if (it + 2 < NIT) load_stage(sb + slot2 * STG, Abase, Bbase, it + 2, tid);
        CP_COMMIT();

        const uint32_t st = sb + slot * STG;
        #pragma unroll
        for (int ks = 0; ks < 2; ks++) {
            uint32_t a[2][4], b[2][4];
            #pragma unroll
            for (int i = 0; i < 2; i++)
                ldm_x4(a[i][0], a[i][1], a[i][2], a[i][3], st + aoff[i] + ks * 32);
            #pragma unroll
            for (int j = 0; j < 2; j++)
                ldm_x4(b[j][0], b[j][1], b[j][2], b[j][3], st + boff[j] + ks * 32);
            #pragma unroll
            for (int i = 0; i < 2; i++) {
                #pragma unroll
                for (int j = 0; j < 2; j++) {
                    mma16816(acc[i*4 + 2*j][0], acc[i*4 + 2*j][1], acc[i*4 + 2*j][2], acc[i*4 + 2*j][3],
                             a[i][0], a[i][1], a[i][2], a[i][3], b[j][0], b[j][2]);
                    mma16816(acc[i*4 + 2*j+1][0], acc[i*4 + 2*j+1][1], acc[i*4 + 2*j+1][2], acc[i*4 + 2*j+1][3],
                             a[i][0], a[i][1], a[i][2], a[i][3], b[j][1], b[j][3]);
                }
            }
        }
    }
}

// ---------------- fused QKV GEMM: 128x64, grid (48, 64), 4 CTAs/SM ----------------
__global__ void __launch_bounds__(256, 4)
gemm_qkv(const __half* __restrict__ Aq, const __half* __restrict__ Wall,
         const float* __restrict__ bq, const float* __restrict__ bk, const float* __restrict__ bv,
         float* __restrict__ Qp, float* __restrict__ Kp, float* __restrict__ Vp)
{
    extern __shared__ __align__(128) char smem[];
    const uint32_t sb = smem_u32(smem);
    const int tid = threadIdx.x;
    const int wid = tid >> 5, lane = tid & 31;
    const int wm = wid >> 1, wn = wid & 1;         // 4x2 warp grid, 32x32 tiles
    const int bm = blockIdx.y * TILE_M;
    const int bn = blockIdx.x * TILE_N;            // 0..3071

    const __half* Abase = Aq + (size_t)bm * KD;
    const __half* Bbase = Wall + (size_t)bn * KD;

    const int lr = lane & 15, lc = lane >> 4;
    uint32_t aoff[2], boff[2];
    #pragma unroll
    for (int i = 0; i < 2; i++)
        aoff[i] = (uint32_t)(((wm * 32 + i * 16 + lr) * RS + lc * 8) * 2);
    #pragma unroll
    for (int j = 0; j < 2; j++)
        boff[j] = (uint32_t)(ST_A + ((wn * 32 + j * 16 + lr) * RS + lc * 8) * 2);

    float acc[8][4];
    #pragma unroll
    for (int t = 0; t < 8; t++)
        #pragma unroll
        for (int q = 0; q < 4; q++) acc[t][q] = 0.f;

    gemm_mainloop(sb, Abase, Bbase, tid, aoff, boff, acc);

    const int sel = bn >> 10;
    const float* bias = (sel == 0) ? bq : (sel == 1) ? bk : bv;
    float* C = (sel == 0) ? Qp : (sel == 1) ? Kp : Vp;
    const int cw = bn & 1023;

    const int g = lane >> 2, t4 = (lane & 3) * 2;
    #pragma unroll
    for (int i = 0; i < 2; i++) {
        #pragma unroll
        for (int j = 0; j < 4; j++) {
            const int col = cw + wn * 32 + j * 8 + t4;
            const float bx = bias[col], by = bias[col + 1];
            #pragma unroll
            for (int h = 0; h < 2; h++) {
                const size_t row = (size_t)(bm + wm * 32 + i * 16 + g + h * 8);
                *(float2*)&C[row * ND + col] =
                    make_float2(acc[i*4 + j][h*2 + 0] + bx, acc[i*4 + j][h*2 + 1] + by);
            }
        }
    }
}

// ---------------- FF GEMM: 128x64 tiles, grid (16, 64), 4 CTAs/SM ----------------
// EPI 1 = +bias+GELU -> fp16 C2; EPI 2 = +bias+residual -> fp32 C
template<int EPI>
__global__ void __launch_bounds__(256, 4)
gemm_ff(const __half* __restrict__ Aq, const __half* __restrict__ Bq,
        const float* __restrict__ bias, const float* __restrict__ Rres,
        float* __restrict__ C, __half* __restrict__ C2)
{
    extern __shared__ __align__(128) char smem[];
    const uint32_t sb = smem_u32(smem);
    const int tid = threadIdx.x;
    const int wid = tid >> 5, lane = tid & 31;
    const int wm = wid >> 1, wn = wid & 1;
    const int bm = blockIdx.y * TILE_M;
    const int bn = blockIdx.x * TILE_N;

    const __half* Abase = Aq + (size_t)bm * KD;
    const __half* Bbase = Bq + (size_t)bn * KD;

    const int lr = lane & 15, lc = lane >> 4;
    uint32_t aoff[2], boff[2];
    #pragma unroll
    for (int i = 0; i < 2; i++)
        aoff[i] = (uint32_t)(((wm * 32 + i * 16 + lr) * RS + lc * 8) * 2);
    #pragma unroll
    for (int j = 0; j < 2; j++)
        boff[j] = (uint32_t)(ST_A + ((wn * 32 + j * 16 + lr) * RS + lc * 8) * 2);

    float acc[8][4];
    #pragma unroll
    for (int t = 0; t < 8; t++)
        #pragma unroll
        for (int q = 0; q < 4; q++) acc[t][q] = 0.f;

    gemm_mainloop(sb, Abase, Bbase, tid, aoff, boff, acc);

    const int g = lane >> 2, t4 = (lane & 3) * 2;
    #pragma unroll
    for (int i = 0; i < 2; i++) {
        #pragma unroll
        for (int j = 0; j < 4; j++) {
            const int col = bn + wn * 32 + j * 8 + t4;
            const float bx = bias[col], by = bias[col + 1];
            #pragma unroll
            for (int h = 0; h < 2; h++) {
                const size_t row = (size_t)(bm + wm * 32 + i * 16 + g + h * 8);
                float vx = acc[i*4 + j][h*2 + 0] + bx;
                float vy = acc[i*4 + j][h*2 + 1] + by;
                if (EPI == 1) {
                    vx = gelu_exact(vx); vy = gelu_exact(vy);
                    half_store(C2, row, col, vx, vy);
                } else {
                    const float2 rv = *(const float2*)&Rres[row * ND + col];
                    *(float2*)&C[row * ND + col] = make_float2(vx + rv.x, vy + rv.y);
                }
            }
        }
    }
}

// ---------------- fused attention: 128 threads, sA aliased onto sK, 8 blocks/SM ----------------
__global__ void __launch_bounds__(128, 8)
attn_fused(const float* __restrict__ Q, const float* __restrict__ K,
           const float* __restrict__ V, const float* __restrict__ lp,
           const float* __restrict__ g2, const float* __restrict__ g3,
           float* __restrict__ yp, __half* __restrict__ yh)
{
    __shared__ float sQ[1024], sK[1024], sV[1024];
    __shared__ float skv[64 * 64];
    __shared__ float sS[16];
    __shared__ float sp[4];
    __shared__ float sscale;
    float* sA = sK;                               // sK dead after kv-loop
    int pos = blockIdx.x, tid = threadIdx.x;      // 128 threads
    size_t base = (size_t)pos * 1024;

    #pragma unroll
    for (int i = 0; i < 2; i++) {
        int idx = tid + i * 128;
        float4 q = ((const float4*)(Q + base))[idx];
        float4 k = ((const float4*)(K + base))[idx];
        float4 v = ((const float4*)(V + base))[idx];
        float qe[4] = {q.x, q.y, q.z, q.w}, ke[4] = {k.x, k.y, k.z, k.w};
        #pragma unroll
        for (int j = 0; j < 4; j++) {
            qe[j] = (qe[j] > 0.f) ? qe[j] : expm1f(qe[j]);
            ke[j] = (ke[j] > 0.f) ? ke[j] : expm1f(ke[j]);
        }
        *(float4*)&sQ[idx*4] = make_float4(qe[0], qe[1], qe[2], qe[3]);
        *(float4*)&sK[idx*4] = make_float4(ke[0], ke[1], ke[2], ke[3]);
        *(float4*)&sV[idx*4] = v;
    }
    __syncthreads();

    // kv[d][e] = SCALE * sum_h phi(K)[h,d] * V[h,e]
    {
        const int d0 = (tid >> 4) * 4;
        const int d1 = d0 + 32;
        const int e4 = (tid & 15) * 4;
        float4 a0 = make_float4(0.f,0.f,0.f,0.f), a1 = a0, a2 = a0, a3 = a0;
        float4 b0 = a0, b1 = a0, b2 = a0, b3 = a0;
        #pragma unroll
        for (int h = 0; h < 16; h++) {
            float4 vv = *(const float4*)&sV[h * 64 + e4];
            float4 k0 = *(const float4*)&sK[h * 64 + d0];
            float4 k1 = *(const float4*)&sK[h * 64 + d1];
            a0.x += k0.x * vv.x; a0.y += k0.x * vv.y; a0.z += k0.x * vv.z; a0.w += k0.x * vv.w;
            a1.x += k0.y * vv.x; a1.y += k0.y * vv.y; a1.z += k0.y * vv.z; a1.w += k0.y * vv.w;
            a2.x += k0.z * vv.x; a2.y += k0.z * vv.y; a2.z += k0.z * vv.z; a2.w += k0.z * vv.w;
            a3.x += k0.w * vv.x; a3.y += k0.w * vv.y; a3.z += k0.w * vv.z; a3.w += k0.w * vv.w;
            b0.x += k1.x * vv.x; b0.y += k1.x * vv.y; b0.z += k1.x * vv.z; b0.w += k1.x * vv.w;
            b1.x += k1.y * vv.x; b1.y += k1.y * vv.y; b1.z += k1.y * vv.z; b1.w += k1.y * vv.w;
            b2.x += k1.z * vv.x; b2.y += k1.z * vv.y; b2.z += k1.z * vv.z; b2.w += k1.z * vv.w;
            b3.x += k1.w * vv.x; b3.y += k1.w * vv.y; b3.z += k1.w * vv.z; b3.w += k1.w * vv.w;
        }
        #define SCL(t) t.x *= SCALE_ATT; t.y *= SCALE_ATT; t.z *= SCALE_ATT; t.w *= SCALE_ATT
        SCL(a0); SCL(a1); SCL(a2); SCL(a3); SCL(b0); SCL(b1); SCL(b2); SCL(b3);
        #undef SCL
        *(float4*)&skv[(d0+0) * 64 + e4] = a0;
        *(float4*)&skv[(d0+1) * 64 + e4] = a1;
        *(float4*)&skv[(d0+2) * 64 + e4] = a2;
        *(float4*)&skv[(d0+3) * 64 + e4] = a3;
        *(float4*)&skv[(d1+0) * 64 + e4] = b0;
        *(float4*)&skv[(d1+1) * 64 + e4] = b1;
        *(float4*)&skv[(d1+2) * 64 + e4] = b2;
        *(float4*)&skv[(d1+3) * 64 + e4] = b3;
    }
    __syncthreads();

    float lam = expf(lp[0] * lp[1]) - expf(lp[2] * lp[3]) + LAM_INIT;

    // a[h][e4]: heads hA and hA+8 per thread (share skv loads)
    {
        const int hA = tid >> 4;
        const int e4 = (tid & 15) * 4;
        float4 s1a = make_float4(0.f,0.f,0.f,0.f), s2a = s1a;
        float4 s1b = s1a, s2b = s1a;
        #pragma unroll
        for (int dd = 0; dd < 8; dd++) {
            float4 q1a = *(const float4*)&sQ[hA * 64 + dd * 4];
            float4 q2a = *(const float4*)&sQ[hA * 64 + 32 + dd * 4];
            float4 q1b = *(const float4*)&sQ[(hA + 8) * 64 + dd * 4];
            float4 q2b = *(const float4*)&sQ[(hA + 8) * 64 + 32 + dd * 4];
            float qa1[4] = {q1a.x, q1a.y, q1a.z, q1a.w};
            float qa2[4] = {q2a.x, q2a.y, q2a.z, q2a.w};
            float qb1[4] = {q1b.x, q1b.y, q1b.z, q1b.w};
            float qb2[4] = {q2b.x, q2b.y, q2b.z, q2b.w};
            #pragma unroll
            for (int j = 0; j < 4; j++) {
                int d = dd * 4 + j;
                float4 f1 = *(const float4*)&skv[d * 64 + e4];
                float4 f2 = *(const float4*)&skv[(32 + d) * 64 + e4];
                s1a.x += qa1[j] * f1.x; s1a.y += qa1[j] * f1.y;
                s1a.z += qa1[j] * f1.z; s1a.w += qa1[j] * f1.w;
                s2a.x += qa2[j] * f2.x; s2a.y += qa2[j] * f2.y;
                s2a.z += qa2[j] * f2.z; s2a.w += qa2[j] * f2.w;
                s1b.x += qb1[j] * f1.x; s1b.y += qb1[j] * f1.y;
                s1b.z += qb1[j] * f1.z; s1b.w += qb1[j] * f1.w;
                s2b.x += qb2[j] * f2.x; s2b.y += qb2[j] * f2.y;
                s2b.z += qb2[j] * f2.z; s2b.w += qb2[j] * f2.w;
            }
        }
        float4 ra, rb;
        ra.x = s1a.x - lam * s2a.x; ra.y = s1a.y - lam * s2a.y;
        ra.z = s1a.z - lam * s2a.z; ra.w = s1a.w - lam * s2a.w;
        rb.x = s1b.x - lam * s2b.x; rb.y = s1b.y - lam * s2b.y;
        rb.z = s1b.z - lam * s2b.z; rb.w = s1b.w - lam * s2b.w;
        *(float4*)&sA[hA * 64 + e4]       = ra;
        *(float4*)&sA[(hA + 8) * 64 + e4] = rb;
    }
    __syncthreads();

    if (tid < 16) {
        float ss = 0.f;
        #pragma unroll
        for (int e = 0; e < 16; e++) {
            float4 v = *(const float4*)&sA[tid * 64 + e * 4];
            ss += v.x*v.x + v.y*v.y + v.z*v.z + v.w*v.w;
        }
        sS[tid] = rsqrtf(ss * (1.0f/64.0f) + EPSF) * ONE_MINUS_LAM_INIT;
    }
    __syncthreads();

    const int i0 = tid * 8;
    const int hh = i0 >> 6;
    float v0[8];
    float ss = 0.f;
    {
        float s = sS[hh];
        #pragma unroll
        for (int half = 0; half < 2; half++) {
            float4 av = *(const float4*)&sA[i0 + half * 4];
            float4 gg = *(const float4*)&g2[(i0 + half * 4) & 63];
            v0[half*4+0] = av.x * s * gg.x; v0[half*4+1] = av.y * s * gg.y;
            v0[half*4+2] = av.z * s * gg.z; v0[half*4+3] = av.w * s * gg.w;
        }
        #pragma unroll
        for (int j = 0; j < 8; j++) ss += v0[j] * v0[j];
    }
    #pragma unroll
    for (int o = 16; o > 0; o >>= 1) ss += __shfl_xor_sync(0xffffffffu, ss, o);
    if ((tid & 31) == 0) sp[tid >> 5] = ss;
    __syncthreads();
    if (tid == 0) {
        float s = sp[0] + sp[1] + sp[2] + sp[3];
        sscale = rsqrtf(s * (1.0f/1024.0f) + EPSF);
    }
    __syncthreads();
    const float sc = sscale;
    #pragma unroll
    for (int half = 0; half < 2; half++) {
        float4 g3v = ((const float4*)g3)[tid * 2 + half];
        float y0 = v0[half*4+0] * sc * g3v.x + v0[half*4+0];
        float y1 = v0[half*4+1] * sc * g3v.y + v0[half*4+1];
        float y2 = v0[half*4+2] * sc * g3v.z + v0[half*4+2];
        float y3 = v0[half*4+3] * sc * g3v.w + v0[half*4+3];
        ((float4*)(yp + base))[tid * 2 + half] = make_float4(y0, y1, y2, y3);
        half_store(yh, (size_t)pos, i0 + half * 4,     y0, y1);
        half_store(yh, (size_t)pos, i0 + half * 4 + 2, y2, y3);
    }
}

// ============================================================
extern "C" void kernel_launch(void* const* d_in, const int* in_sizes, int n_in,
                              void* d_out, int out_size)
{
    const float* x   = (const float*)d_in[0];
    const float* Wq  = (const float*)d_in[1];
    const float* bq  = (const float*)d_in[2];
    const float* Wk  = (const float*)d_in[3];
    const float* bk  = (const float*)d_in[4];
    const float* Wv  = (const float*)d_in[5];
    const float* bv  = (const float*)d_in[6];
    const float* lp  = (const float*)d_in[7];
    const float* g1  = (const float*)d_in[8];
    const float* g2  = (const float*)d_in[9];
    const float* g3  = (const float*)d_in[10];
    const float* Wf1 = (const float*)d_in[11];
    const float* bf1 = (const float*)d_in[12];
    const float* Wf2 = (const float*)d_in[13];
    const float* bf2 = (const float*)d_in[14];
    float* out = (float*)d_out;

    float *Qp, *Kp, *Vp, *yp;
    __half *A1, *A2, *Wall;
    cudaGetSymbolAddress((void**)&Qp, g_Q);
    cudaGetSymbolAddress((void**)&Kp, g_K);
    cudaGetSymbolAddress((void**)&Vp, g_V);
    cudaGetSymbolAddress((void**)&yp, g_y);
    cudaGetSymbolAddress((void**)&A1, g_A1);
    cudaGetSymbolAddress((void**)&A2, g_A2);
    cudaGetSymbolAddress((void**)&Wall, g_W);

    cudaFuncSetAttribute(gemm_qkv,   cudaFuncAttributeMaxDynamicSharedMemorySize, SMEM_DYN);
    cudaFuncSetAttribute(gemm_ff<1>, cudaFuncAttributeMaxDynamicSharedMemorySize, SMEM_DYN);
    cudaFuncSetAttribute(gemm_ff<2>, cudaFuncAttributeMaxDynamicSharedMemorySize, SMEM_DYN);

    prep_k<<<M_TOT + 1280, 256>>>(x, g1, A1, Wq, Wk, Wv, Wf1, Wf2, Wall);

    gemm_qkv<<<dim3(48, 64), 256, SMEM_DYN>>>(A1, Wall, bq, bk, bv, Qp, Kp, Vp);

    attn_fused<<<M_TOT, 128>>>(Qp, Kp, Vp, lp, g2, g3, yp, A1);

    gemm_ff<1><<<dim3(16, 64), 256, SMEM_DYN>>>(A1, Wall + 3*WMAT, bf1, nullptr, nullptr, A2);
    gemm_ff<2><<<dim3(16, 64), 256, SMEM_DYN>>>(A2, Wall + 4*WMAT, bf2, yp, out, nullptr);
}

// round 15
// speedup vs baseline: 1.0471x; 1.0471x over previous
#include <cuda_runtime.h>
#include <cuda_fp16.h>
#include <math.h>
#include <stdint.h>

// ---------------- problem constants ----------------
#define M_TOT 8192
#define KD    1024
#define ND    1024
#define EPSF  1.1920929e-07f
#define LAM_INIT 0.2f
#define ONE_MINUS_LAM_INIT 0.8f
#define SCALE_ATT 0.044194173824159216f

// ---------------- GEMM tiling: 128x64 tile, KC=32, 3 CTAs/SM ----------------
#define TILE_M 128
#define TILE_N 64
#define KC     32
#define NIT    (KD/KC)             // 32
#define RS     40                  // smem row stride in halves (32 + 8 pad)
#define ST_A   (128*RS*2)          // 10240 B
#define ST_B   (64*RS*2)           // 5120 B
#define STG    (ST_A + ST_B)       // 15360 B per stage
#define SMEM_DYN (3*STG)           // 46080 -> 3 CTAs/SM

#define WMAT   ((size_t)1048576)

// ---------------- scratch (__device__ globals; no allocs allowed) ----------------
__device__ __align__(128) __half g_Qh[(size_t)M_TOT * ND];   // 16MB fp16 Q
__device__ __align__(128) __half g_Kh[(size_t)M_TOT * ND];   // 16MB fp16 K
__device__ __align__(128) __half g_Vh[(size_t)M_TOT * ND];   // 16MB fp16 V
__device__ float g_y [(size_t)M_TOT * ND];                   // rmsnorm3 + residual (fp32)
__device__ __align__(128) __half g_A1[(size_t)M_TOT * KD];   // 16MB fp16 activations
__device__ __align__(128) __half g_A2[(size_t)M_TOT * KD];   // 16MB fp16 h
__device__ __align__(128) __half g_W [5 * WMAT];             // 10MB: Wq|Wk|Wv|Wf1|Wf2

// ---------------- PTX helpers ----------------
__device__ __forceinline__ uint32_t smem_u32(const void* p) {
    uint32_t a;
    asm("{ .reg .u64 t; cvta.to.shared.u64 t, %1; cvt.u32.u64 %0, t; }" : "=r"(a) : "l"(p));
    return a;
}
#define CP_ASYNC16(dst, src) \
    asm volatile("cp.async.cg.shared.global [%0], [%1], 16;" :: "r"(dst), "l"(src) : "memory")
#define CP_COMMIT() asm volatile("cp.async.commit_group;" ::: "memory")
#define CP_WAIT1()  asm volatile("cp.async.wait_group 1;" ::: "memory")

__device__ __forceinline__ void ldm_x4(uint32_t& r0, uint32_t& r1, uint32_t& r2, uint32_t& r3,
                                       uint32_t addr) {
    asm volatile("ldmatrix.sync.aligned.m8n8.x4.shared.b16 {%0,%1,%2,%3}, [%4];"
                 : "=r"(r0), "=r"(r1), "=r"(r2), "=r"(r3) : "r"(addr));
}
__device__ __forceinline__ void mma16816(float& c0, float& c1, float& c2, float& c3,
                                         uint32_t a0, uint32_t a1, uint32_t a2, uint32_t a3,
                                         uint32_t b0, uint32_t b1) {
    asm volatile("mma.sync.aligned.m16n8k16.row.col.f32.f16.f16.f32 "
                 "{%0,%1,%2,%3}, {%4,%5,%6,%7}, {%8,%9}, {%0,%1,%2,%3};"
                 : "+f"(c0), "+f"(c1), "+f"(c2), "+f"(c3)
                 : "r"(a0), "r"(a1), "r"(a2), "r"(a3), "r"(b0), "r"(b1));
}

__device__ __forceinline__ void half_store(__half* base, size_t row, int col,
                                           float vx, float vy) {
    __half2 hh; hh.x = __float2half_rn(vx); hh.y = __float2half_rn(vy);
    *(__half2*)&base[row * KD + col] = hh;
}

__device__ __forceinline__ float gelu_exact(float v) {
    return 0.5f * v * (1.0f + erff(v * 0.70710678118654752f));
}

// ---------------- prep: rmsnorm (blocks 0..8191) + weight convert (blocks 8192..9471) ----------------
__global__ void prep_k(const float* __restrict__ x, const float* __restrict__ g1,
                       __half* __restrict__ yh,
                       const float* __restrict__ w0, const float* __restrict__ w1,
                       const float* __restrict__ w2, const float* __restrict__ w3,
                       const float* __restrict__ w4, __half* __restrict__ Wall)
{
    const int tid = threadIdx.x;                   // 256
    if (blockIdx.x < M_TOT) {
        int row = blockIdx.x;
        const float4* xr = (const float4*)(x + (size_t)row * 1024);
        float4 v = xr[tid];
        float ss = v.x*v.x + v.y*v.y + v.z*v.z + v.w*v.w;
        #pragma unroll
        for (int o = 16; o > 0; o >>= 1) ss += __shfl_xor_sync(0xffffffffu, ss, o);
        __shared__ float sp[8];
        __shared__ float sscale;
        if ((tid & 31) == 0) sp[tid >> 5] = ss;
        __syncthreads();
        if (tid == 0) {
            float s = 0.f;
            #pragma unroll
            for (int i = 0; i < 8; i++) s += sp[i];
            sscale = rsqrtf(s * (1.0f/1024.0f) + EPSF);
        }
        __syncthreads();
        float sc = sscale;
        float4 wv = ((const float4*)g1)[tid];
        half_store(yh, (size_t)row, tid * 4,     v.x * sc * wv.x, v.y * sc * wv.y);
        half_store(yh, (size_t)row, tid * 4 + 2, v.z * sc * wv.z, v.w * sc * wv.w);
    } else {
        size_t b = (size_t)(blockIdx.x - M_TOT);   // 0..1279
        #pragma unroll
        for (int r = 0; r < 4; r++) {
            size_t i4 = b * 1024 + (size_t)r * 256 + tid;
            int m = (int)(i4 >> 18);
            const float* src = (m == 0) ? w0 : (m == 1) ? w1 : (m == 2) ? w2
                              : (m == 3) ? w3 : w4;
            float4 v = ((const float4*)src)[i4 & 262143];
            __half2 a; a.x = __float2half_rn(v.x); a.y = __float2half_rn(v.y);
            __half2 c; c.x = __float2half_rn(v.z); c.y = __float2half_rn(v.w);
            uint2 o; o.x = *(uint32_t*)&a; o.y = *(uint32_t*)&c;
            ((uint2*)Wall)[i4] = o;
        }
    }
}

// ---------------- stage loader: 128 A rows + 64 B rows, KC=32 ----------------
__device__ __forceinline__ void load_stage(uint32_t stage, const __half* Ab,
                                           const __half* Bb, int kiter, int tid)
{
    const int k0 = kiter * KC;
    #pragma unroll
    for (int i = 0; i < 3; i++) {
        int idx = tid + i * 256;
        if (i < 2) {
            int r = idx >> 2, c = idx & 3;
            CP_ASYNC16(stage + (uint32_t)(r * (RS*2) + c * 16),
                       Ab + (size_t)r * KD + k0 + c * 8);
        } else {
            int j = idx - 512;
            int r = j >> 2, c = j & 3;
            CP_ASYNC16(stage + ST_A + (uint32_t)(r * (RS*2) + c * 16),
                       Bb + (size_t)r * KD + k0 + c * 8);
        }
    }
}

// ---------------- shared GEMM mainloop, fully unrolled (32x32 warp tiles) ----------------
__device__ __forceinline__ void gemm_mainloop(uint32_t sb, const __half* Abase,
                                              const __half* Bbase, int tid,
                                              const uint32_t* aoff, const uint32_t* boff,
                                              float acc[8][4])
{
    load_stage(sb,       Abase, Bbase, 0, tid); CP_COMMIT();
    load_stage(sb + STG, Abase, Bbase, 1, tid); CP_COMMIT();

    #pragma unroll
    for (int it = 0; it < NIT; it++) {
        const int slot  = it % 3;
        const int slot2 = (it + 2) % 3;
        CP_WAIT1();
        __syncthreads();
        if (it + 2 < NIT) load_stage(sb + slot2 * STG, Abase, Bbase, it + 2, tid);
        CP_COMMIT();

        const uint32_t st = sb + slot * STG;
        #pragma unroll
        for (int ks = 0; ks < 2; ks++) {
            uint32_t a[2][4], b[2][4];
            #pragma unroll
            for (int i = 0; i < 2; i++)
                ldm_x4(a[i][0], a[i][1], a[i][2], a[i][3], st + aoff[i] + ks * 32);
            #pragma unroll
            for (int j = 0; j < 2; j++)
                ldm_x4(b[j][0], b[j][1], b[j][2], b[j][3], st + boff[j] + ks * 32);
            #pragma unroll
            for (int i = 0; i < 2; i++) {
                #pragma unroll
                for (int j = 0; j < 2; j++) {
                    mma16816(acc[i*4 + 2*j][0], acc[i*4 + 2*j][1], acc[i*4 + 2*j][2], acc[i*4 + 2*j][3],
                             a[i][0], a[i][1], a[i][2], a[i][3], b[j][0], b[j][2]);
                    mma16816(acc[i*4 + 2*j+1][0], acc[i*4 + 2*j+1][1], acc[i*4 + 2*j+1][2], acc[i*4 + 2*j+1][3],
                             a[i][0], a[i][1], a[i][2], a[i][3], b[j][1], b[j][3]);
                }
            }
        }
    }
}

// ---------------- fused QKV GEMM: 128x64, grid (48, 64), fp16 outputs ----------------
__global__ void __launch_bounds__(256, 3)
gemm_qkv(const __half* __restrict__ Aq, const __half* __restrict__ Wall,
         const float* __restrict__ bq, const float* __restrict__ bk, const float* __restrict__ bv,
         __half* __restrict__ Qp, __half* __restrict__ Kp, __half* __restrict__ Vp)
{
    extern __shared__ __align__(128) char smem[];
    const uint32_t sb = smem_u32(smem);
    const int tid = threadIdx.x;
    const int wid = tid >> 5, lane = tid & 31;
    const int wm = wid >> 1, wn = wid & 1;
    const int bm = blockIdx.y * TILE_M;
    const int bn = blockIdx.x * TILE_N;            // 0..3071

    const __half* Abase = Aq + (size_t)bm * KD;
    const __half* Bbase = Wall + (size_t)bn * KD;

    const int lr = lane & 15, lc = lane >> 4;
    uint32_t aoff[2], boff[2];
    #pragma unroll
    for (int i = 0; i < 2; i++)
        aoff[i] = (uint32_t)(((wm * 32 + i * 16 + lr) * RS + lc * 8) * 2);
    #pragma unroll
    for (int j = 0; j < 2; j++)
        boff[j] = (uint32_t)(ST_A + ((wn * 32 + j * 16 + lr) * RS + lc * 8) * 2);

    float acc[8][4];
    #pragma unroll
    for (int t = 0; t < 8; t++)
        #pragma unroll
        for (int q = 0; q < 4; q++) acc[t][q] = 0.f;

    gemm_mainloop(sb, Abase, Bbase, tid, aoff, boff, acc);

    const int sel = bn >> 10;
    const float* bias = (sel == 0) ? bq : (sel == 1) ? bk : bv;
    __half* C = (sel == 0) ? Qp : (sel == 1) ? Kp : Vp;
    const int cw = bn & 1023;

    const int g = lane >> 2, t4 = (lane & 3) * 2;
    #pragma unroll
    for (int i = 0; i < 2; i++) {
        #pragma unroll
        for (int j = 0; j < 4; j++) {
            const int col = cw + wn * 32 + j * 8 + t4;
            const float bx = bias[col], by = bias[col + 1];
            #pragma unroll
            for (int h = 0; h < 2; h++) {
                const size_t row = (size_t)(bm + wm * 32 + i * 16 + g + h * 8);
                half_store(C, row, col, acc[i*4 + j][h*2 + 0] + bx, acc[i*4 + j][h*2 + 1] + by);
            }
        }
    }
}

// ---------------- FF GEMM: 128x64 tiles, grid (16, 64), 3 CTAs/SM ----------------
// EPI 1 = +bias+GELU -> fp16 C2; EPI 2 = +bias+residual -> fp32 C
template<int EPI>
__global__ void __launch_bounds__(256, 3)
gemm_ff(const __half* __restrict__ Aq, const __half* __restrict__ Bq,
        const float* __restrict__ bias, const float* __restrict__ Rres,
        float* __restrict__ C, __half* __restrict__ C2)
{
    extern __shared__ __align__(128) char smem[];
    const uint32_t sb = smem_u32(smem);
    const int tid = threadIdx.x;
    const int wid = tid >> 5, lane = tid & 31;
    const int wm = wid >> 1, wn = wid & 1;
    const int bm = blockIdx.y * TILE_M;
    const int bn = blockIdx.x * TILE_N;

    const __half* Abase = Aq + (size_t)bm * KD;
    const __half* Bbase = Bq + (size_t)bn * KD;

    const int lr = lane & 15, lc = lane >> 4;
    uint32_t aoff[2], boff[2];
    #pragma unroll
    for (int i = 0; i < 2; i++)
        aoff[i] = (uint32_t)(((wm * 32 + i * 16 + lr) * RS + lc * 8) * 2);
    #pragma unroll
    for (int j = 0; j < 2; j++)
        boff[j] = (uint32_t)(ST_A + ((wn * 32 + j * 16 + lr) * RS + lc * 8) * 2);

    float acc[8][4];
    #pragma unroll
    for (int t = 0; t < 8; t++)
        #pragma unroll
        for (int q = 0; q < 4; q++) acc[t][q] = 0.f;

    gemm_mainloop(sb, Abase, Bbase, tid, aoff, boff, acc);

    const int g = lane >> 2, t4 = (lane & 3) * 2;
    #pragma unroll
    for (int i = 0; i < 2; i++) {
        #pragma unroll
        for (int j = 0; j < 4; j++) {
            const int col = bn + wn * 32 + j * 8 + t4;
            const float bx = bias[col], by = bias[col + 1];
            #pragma unroll
            for (int h = 0; h < 2; h++) {
                const size_t row = (size_t)(bm + wm * 32 + i * 16 + g + h * 8);
                float vx = acc[i*4 + j][h*2 + 0] + bx;
                float vy = acc[i*4 + j][h*2 + 1] + by;
                if (EPI == 1) {
                    vx = gelu_exact(vx); vy = gelu_exact(vy);
                    half_store(C2, row, col, vx, vy);
                } else {
                    const float2 rv = *(const float2*)&Rres[row * ND + col];
                    *(float2*)&C[row * ND + col] = make_float2(vx + rv.x, vy + rv.y);
                }
            }
        }
    }
}

// ---------------- fused attention: 128 threads, fp16 inputs, 8 blocks/SM ----------------
__global__ void __launch_bounds__(128, 8)
attn_fused(const __half* __restrict__ Q, const __half* __restrict__ K,
           const __half* __restrict__ V, const float* __restrict__ lp,
           const float* __restrict__ g2, const float* __restrict__ g3,
           float* __restrict__ yp, __half* __restrict__ yh)
{
    __shared__ float sQ[1024], sK[1024], sV[1024];
    __shared__ float skv[64 * 64];
    __shared__ float sS[16];
    __shared__ float sp[4];
    __shared__ float sscale;
    float* sA = sK;                               // sK dead after kv-loop
    int pos = blockIdx.x, tid = threadIdx.x;      // 128 threads
    size_t base = (size_t)pos * 1024;

    {   // load 8 halves (one uint4) per tensor per thread, convert + elu
        const uint4 qv = ((const uint4*)(Q + base))[tid];
        const uint4 kv = ((const uint4*)(K + base))[tid];
        const uint4 vv = ((const uint4*)(V + base))[tid];
        const __half2* qh = (const __half2*)&qv;
        const __half2* kh = (const __half2*)&kv;
        const __half2* vh = (const __half2*)&vv;
        float q8[8], k8[8], v8[8];
        #pragma unroll
        for (int p = 0; p < 4; p++) {
            float2 fq = __half22float2(qh[p]);
            float2 fk = __half22float2(kh[p]);
            float2 fv = __half22float2(vh[p]);
            q8[p*2+0] = (fq.x > 0.f) ? fq.x : expm1f(fq.x);
            q8[p*2+1] = (fq.y > 0.f) ? fq.y : expm1f(fq.y);
            k8[p*2+0] = (fk.x > 0.f) ? fk.x : expm1f(fk.x);
            k8[p*2+1] = (fk.y > 0.f) ? fk.y : expm1f(fk.y);
            v8[p*2+0] = fv.x; v8[p*2+1] = fv.y;
        }
        *(float4*)&sQ[tid*8]     = *(float4*)&q8[0];
        *(float4*)&sQ[tid*8 + 4] = *(float4*)&q8[4];
        *(float4*)&sK[tid*8]     = *(float4*)&k8[0];
        *(float4*)&sK[tid*8 + 4] = *(float4*)&k8[4];
        *(float4*)&sV[tid*8]     = *(float4*)&v8[0];
        *(float4*)&sV[tid*8 + 4] = *(float4*)&v8[4];
    }
    __syncthreads();

    // kv[d][e] = SCALE * sum_h phi(K)[h,d] * V[h,e]
    {
        const int d0 = (tid >> 4) * 4;
        const int d1 = d0 + 32;
        const int e4 = (tid & 15) * 4;
        float4 a0 = make_float4(0.f,0.f,0.f,0.f), a1 = a0, a2 = a0, a3 = a0;
        float4 b0 = a0, b1 = a0, b2 = a0, b3 = a0;
        #pragma unroll
        for (int h = 0; h < 16; h++) {
            float4 vv = *(const float4*)&sV[h * 64 + e4];
            float4 k0 = *(const float4*)&sK[h * 64 + d0];
            float4 k1 = *(const float4*)&sK[h * 64 + d1];
            a0.x += k0.x * vv.x; a0.y += k0.x * vv.y; a0.z += k0.x * vv.z; a0.w += k0.x * vv.w;
            a1.x += k0.y * vv.x; a1.y += k0.y * vv.y; a1.z += k0.y * vv.z; a1.w += k0.y * vv.w;
            a2.x += k0.z * vv.x; a2.y += k0.z * vv.y; a2.z += k0.z * vv.z; a2.w += k0.z * vv.w;
            a3.x += k0.w * vv.x; a3.y += k0.w * vv.y; a3.z += k0.w * vv.z; a3.w += k0.w * vv.w;
            b0.x += k1.x * vv.x; b0.y += k1.x * vv.y; b0.z += k1.x * vv.z; b0.w += k1.x * vv.w;
            b1.x += k1.y * vv.x; b1.y += k1.y * vv.y; b1.z += k1.y * vv.z; b1.w += k1.y * vv.w;
            b2.x += k1.z * vv.x; b2.y += k1.z * vv.y; b2.z += k1.z * vv.z; b2.w += k1.z * vv.w;
            b3.x += k1.w * vv.x; b3.y += k1.w * vv.y; b3.z += k1.w * vv.z; b3.w += k1.w * vv.w;
        }
        #define SCL(t) t.x *= SCALE_ATT; t.y *= SCALE_ATT; t.z *= SCALE_ATT; t.w *= SCALE_ATT
        SCL(a0); SCL(a1); SCL(a2); SCL(a3); SCL(b0); SCL(b1); SCL(b2); SCL(b3);
        #undef SCL
        *(float4*)&skv[(d0+0) * 64 + e4] = a0;
        *(float4*)&skv[(d0+1) * 64 + e4] = a1;
        *(float4*)&skv[(d0+2) * 64 + e4] = a2;
        *(float4*)&skv[(d0+3) * 64 + e4] = a3;
        *(float4*)&skv[(d1+0) * 64 + e4] = b0;
        *(float4*)&skv[(d1+1) * 64 + e4] = b1;
        *(float4*)&skv[(d1+2) * 64 + e4] = b2;
        *(float4*)&skv[(d1+3) * 64 + e4] = b3;
    }
    __syncthreads();

    float lam = expf(lp[0] * lp[1]) - expf(lp[2] * lp[3]) + LAM_INIT;

    // a[h][e4]: heads hA and hA+8 per thread (share skv loads)
    {
        const int hA = tid >> 4;
        const int e4 = (tid & 15) * 4;
        float4 s1a = make_float4(0.f,0.f,0.f,0.f), s2a = s1a;
        float4 s1b = s1a, s2b = s1a;
        #pragma unroll
        for (int dd = 0; dd < 8; dd++) {
            float4 q1a = *(const float4*)&sQ[hA * 64 + dd * 4];
            float4 q2a = *(const float4*)&sQ[hA * 64 + 32 + dd * 4];
            float4 q1b = *(const float4*)&sQ[(hA + 8) * 64 + dd * 4];
            float4 q2b = *(const float4*)&sQ[(hA + 8) * 64 + 32 + dd * 4];
            float qa1[4] = {q1a.x, q1a.y, q1a.z, q1a.w};
            float qa2[4] = {q2a.x, q2a.y, q2a.z, q2a.w};
            float qb1[4] = {q1b.x, q1b.y, q1b.z, q1b.w};
            float qb2[4] = {q2b.x, q2b.y, q2b.z, q2b.w};
            #pragma unroll
            for (int j = 0; j < 4; j++) {
                int d = dd * 4 + j;
                float4 f1 = *(const float4*)&skv[d * 64 + e4];
                float4 f2 = *(const float4*)&skv[(32 + d) * 64 + e4];
                s1a.x += qa1[j] * f1.x; s1a.y += qa1[j] * f1.y;
                s1a.z += qa1[j] * f1.z; s1a.w += qa1[j] * f1.w;
                s2a.x += qa2[j] * f2.x; s2a.y += qa2[j] * f2.y;
                s2a.z += qa2[j] * f2.z; s2a.w += qa2[j] * f2.w;
                s1b.x += qb1[j] * f1.x; s1b.y += qb1[j] * f1.y;
                s1b.z += qb1[j] * f1.z; s1b.w += qb1[j] * f1.w;
                s2b.x += qb2[j] * f2.x; s2b.y += qb2[j] * f2.y;
                s2b.z += qb2[j] * f2.z; s2b.w += qb2[j] * f2.w;
            }
        }
        float4 ra, rb;
        ra.x = s1a.x - lam * s2a.x; ra.y = s1a.y - lam * s2a.y;
        ra.z = s1a.z - lam * s2a.z; ra.w = s1a.w - lam * s2a.w;
        rb.x = s1b.x - lam * s2b.x; rb.y = s1b.y - lam * s2b.y;
        rb.z = s1b.z - lam * s2b.z; rb.w = s1b.w - lam * s2b.w;
        *(float4*)&sA[hA * 64 + e4]       = ra;
        *(float4*)&sA[(hA + 8) * 64 + e4] = rb;
    }
    __syncthreads();

    if (tid < 16) {
        float ss = 0.f;
        #pragma unroll
        for (int e = 0; e < 16; e++) {
            float4 v = *(const float4*)&sA[tid * 64 + e * 4];
            ss += v.x*v.x + v.y*v.y + v.z*v.z + v.w*v.w;
        }
        sS[tid] = rsqrtf(ss * (1.0f/64.0f) + EPSF) * ONE_MINUS_LAM_INIT;
    }
    __syncthreads();

    const int i0 = tid * 8;
    const int hh = i0 >> 6;
    float v0[8];
    float ss = 0.f;
    {
        float s = sS[hh];
        #pragma unroll
        for (int half = 0; half < 2; half++) {
            float4 av = *(const float4*)&sA[i0 + half * 4];
            float4 gg = *(const float4*)&g2[(i0 + half * 4) & 63];
            v0[half*4+0] = av.x * s * gg.x; v0[half*4+1] = av.y * s * gg.y;
            v0[half*4+2] = av.z * s * gg.z; v0[half*4+3] = av.w * s * gg.w;
        }
        #pragma unroll
        for (int j = 0; j < 8; j++) ss += v0[j] * v0[j];
    }
    #pragma unroll
    for (int o = 16; o > 0; o >>= 1) ss += __shfl_xor_sync(0xffffffffu, ss, o);
    if ((tid & 31) == 0) sp[tid >> 5] = ss;
    __syncthreads();
    if (tid == 0) {
        float s = sp[0] + sp[1] + sp[2] + sp[3];
        sscale = rsqrtf(s * (1.0f/1024.0f) + EPSF);
    }
    __syncthreads();
    const float sc = sscale;
    #pragma unroll
    for (int half = 0; half < 2; half++) {
        float4 g3v = ((const float4*)g3)[tid * 2 + half];
        float y0 = v0[half*4+0] * sc * g3v.x + v0[half*4+0];
        float y1 = v0[half*4+1] * sc * g3v.y + v0[half*4+1];
        float y2 = v0[half*4+2] * sc * g3v.z + v0[half*4+2];
        float y3 = v0[half*4+3] * sc * g3v.w + v0[half*4+3];
        ((float4*)(yp + base))[tid * 2 + half] = make_float4(y0, y1, y2, y3);
        half_store(yh, (size_t)pos, i0 + half * 4,     y0, y1);
        half_store(yh, (size_t)pos, i0 + half * 4 + 2, y2, y3);
    }
}

// ============================================================
extern "C" void kernel_launch(void* const* d_in, const int* in_sizes, int n_in,
                              void* d_out, int out_size)
{
    const float* x   = (const float*)d_in[0];
    const float* Wq  = (const float*)d_in[1];
    const float* bq  = (const float*)d_in[2];
    const float* Wk  = (const float*)d_in[3];
    const float* bk  = (const float*)d_in[4];
    const float* Wv  = (const float*)d_in[5];
    const float* bv  = (const float*)d_in[6];
    const float* lp  = (const float*)d_in[7];
    const float* g1  = (const float*)d_in[8];
    const float* g2  = (const float*)d_in[9];
    const float* g3  = (const float*)d_in[10];
    const float* Wf1 = (const float*)d_in[11];
    const float* bf1 = (const float*)d_in[12];
    const float* Wf2 = (const float*)d_in[13];
    const float* bf2 = (const float*)d_in[14];
    float* out = (float*)d_out;

    float *yp;
    __half *Qh, *Kh, *Vh, *A1, *A2, *Wall;
    cudaGetSymbolAddress((void**)&Qh, g_Qh);
    cudaGetSymbolAddress((void**)&Kh, g_Kh);
    cudaGetSymbolAddress((void**)&Vh, g_Vh);
    cudaGetSymbolAddress((void**)&yp, g_y);
    cudaGetSymbolAddress((void**)&A1, g_A1);
    cudaGetSymbolAddress((void**)&A2, g_A2);
    cudaGetSymbolAddress((void**)&Wall, g_W);

    cudaFuncSetAttribute(gemm_qkv,   cudaFuncAttributeMaxDynamicSharedMemorySize, SMEM_DYN);
    cudaFuncSetAttribute(gemm_ff<1>, cudaFuncAttributeMaxDynamicSharedMemorySize, SMEM_DYN);
    cudaFuncSetAttribute(gemm_ff<2>, cudaFuncAttributeMaxDynamicSharedMemorySize, SMEM_DYN);

    prep_k<<<M_TOT + 1280, 256>>>(x, g1, A1, Wq, Wk, Wv, Wf1, Wf2, Wall);

    gemm_qkv<<<dim3(48, 64), 256, SMEM_DYN>>>(A1, Wall, bq, bk, bv, Qh, Kh, Vh);

    attn_fused<<<M_TOT, 128>>>(Qh, Kh, Vh, lp, g2, g3, yp, A1);

    gemm_ff<1><<<dim3(16, 64), 256, SMEM_DYN>>>(A1, Wall + 3*WMAT, bf1, nullptr, nullptr, A2);
    gemm_ff<2><<<dim3(16, 64), 256, SMEM_DYN>>>(A2, Wall + 4*WMAT, bf2, yp, out, nullptr);
}

// round 16
// speedup vs baseline: 1.0633x; 1.0155x over previous
#include <cuda_runtime.h>
#include <cuda_fp16.h>
#include <math.h>
#include <stdint.h>

// ---------------- problem constants ----------------
#define M_TOT 8192
#define KD    1024
#define ND    1024
#define EPSF  1.1920929e-07f
#define LAM_INIT 0.2f
#define ONE_MINUS_LAM_INIT 0.8f
#define SCALE_ATT 0.044194173824159216f

// ---------------- GEMM tiling: 128x64 tile, KC=32, 3 CTAs/SM ----------------
#define TILE_M 128
#define TILE_N 64
#define KC     32
#define NIT    (KD/KC)             // 32
#define RS     40                  // smem row stride in halves (32 + 8 pad)
#define ST_A   (128*RS*2)          // 10240 B
#define ST_B   (64*RS*2)           // 5120 B
#define STG    (ST_A + ST_B)       // 15360 B per stage
#define SMEM_DYN (3*STG)           // 46080 -> 3 CTAs/SM

#define WMAT   ((size_t)1048576)

// ---------------- scratch (__device__ globals; no allocs allowed) ----------------
__device__ __align__(128) __half g_Qh[(size_t)M_TOT * ND];   // 16MB fp16 Q
__device__ __align__(128) __half g_Kh[(size_t)M_TOT * ND];   // 16MB fp16 K
__device__ __align__(128) __half g_Vh[(size_t)M_TOT * ND];   // 16MB fp16 V
__device__ __align__(128) __half g_A1[(size_t)M_TOT * KD];   // 16MB fp16 activations / y
__device__ __align__(128) __half g_A2[(size_t)M_TOT * KD];   // 16MB fp16 h
__device__ __align__(128) __half g_W [5 * WMAT];             // 10MB: Wq|Wk|Wv|Wf1|Wf2

// ---------------- PTX helpers ----------------
__device__ __forceinline__ uint32_t smem_u32(const void* p) {
    uint32_t a;
    asm("{ .reg .u64 t; cvta.to.shared.u64 t, %1; cvt.u32.u64 %0, t; }" : "=r"(a) : "l"(p));
    return a;
}
#define CP_ASYNC16(dst, src) \
    asm volatile("cp.async.cg.shared.global [%0], [%1], 16;" :: "r"(dst), "l"(src) : "memory")
#define CP_COMMIT() asm volatile("cp.async.commit_group;" ::: "memory")
#define CP_WAIT1()  asm volatile("cp.async.wait_group 1;" ::: "memory")

__device__ __forceinline__ void ldm_x4(uint32_t& r0, uint32_t& r1, uint32_t& r2, uint32_t& r3,
                                       uint32_t addr) {
    asm volatile("ldmatrix.sync.aligned.m8n8.x4.shared.b16 {%0,%1,%2,%3}, [%4];"
                 : "=r"(r0), "=r"(r1), "=r"(r2), "=r"(r3) : "r"(addr));
}
__device__ __forceinline__ void mma16816(float& c0, float& c1, float& c2, float& c3,
                                         uint32_t a0, uint32_t a1, uint32_t a2, uint32_t a3,
                                         uint32_t b0, uint32_t b1) {
    asm volatile("mma.sync.aligned.m16n8k16.row.col.f32.f16.f16.f32 "
                 "{%0,%1,%2,%3}, {%4,%5,%6,%7}, {%8,%9}, {%0,%1,%2,%3};"
                 : "+f"(c0), "+f"(c1), "+f"(c2), "+f"(c3)
                 : "r"(a0), "r"(a1), "r"(a2), "r"(a3), "r"(b0), "r"(b1));
}

__device__ __forceinline__ void half_store(__half* base, size_t row, int col,
                                           float vx, float vy) {
    __half2 hh; hh.x = __float2half_rn(vx); hh.y = __float2half_rn(vy);
    *(__half2*)&base[row * KD + col] = hh;
}

__device__ __forceinline__ float gelu_exact(float v) {
    return 0.5f * v * (1.0f + erff(v * 0.70710678118654752f));
}

// ---------------- prep: rmsnorm (blocks 0..8191) + weight convert (blocks 8192..9471) ----------------
__global__ void prep_k(const float* __restrict__ x, const float* __restrict__ g1,
                       __half* __restrict__ yh,
                       const float* __restrict__ w0, const float* __restrict__ w1,
                       const float* __restrict__ w2, const float* __restrict__ w3,
                       const float* __restrict__ w4, __half* __restrict__ Wall)
{
    const int tid = threadIdx.x;                   // 256
    if (blockIdx.x < M_TOT) {
        int row = blockIdx.x;
        const float4* xr = (const float4*)(x + (size_t)row * 1024);
        float4 v = xr[tid];
        float ss = v.x*v.x + v.y*v.y + v.z*v.z + v.w*v.w;
        #pragma unroll
        for (int o = 16; o > 0; o >>= 1) ss += __shfl_xor_sync(0xffffffffu, ss, o);
        __shared__ float sp[8];
        __shared__ float sscale;
        if ((tid & 31) == 0) sp[tid >> 5] = ss;
        __syncthreads();
        if (tid == 0) {
            float s = 0.f;
            #pragma unroll
            for (int i = 0; i < 8; i++) s += sp[i];
            sscale = rsqrtf(s * (1.0f/1024.0f) + EPSF);
        }
        __syncthreads();
        float sc = sscale;
        float4 wv = ((const float4*)g1)[tid];
        half_store(yh, (size_t)row, tid * 4,     v.x * sc * wv.x, v.y * sc * wv.y);
        half_store(yh, (size_t)row, tid * 4 + 2, v.z * sc * wv.z, v.w * sc * wv.w);
    } else {
        size_t b = (size_t)(blockIdx.x - M_TOT);   // 0..1279
        #pragma unroll
        for (int r = 0; r < 4; r++) {
            size_t i4 = b * 1024 + (size_t)r * 256 + tid;
            int m = (int)(i4 >> 18);
            const float* src = (m == 0) ? w0 : (m == 1) ? w1 : (m == 2) ? w2
                              : (m == 3) ? w3 : w4;
            float4 v = ((const float4*)src)[i4 & 262143];
            __half2 a; a.x = __float2half_rn(v.x); a.y = __float2half_rn(v.y);
            __half2 c; c.x = __float2half_rn(v.z); c.y = __float2half_rn(v.w);
            uint2 o; o.x = *(uint32_t*)&a; o.y = *(uint32_t*)&c;
            ((uint2*)Wall)[i4] = o;
        }
    }
}

// ---------------- stage loader: 128 A rows + 64 B rows, KC=32 ----------------
__device__ __forceinline__ void load_stage(uint32_t stage, const __half* Ab,
                                           const __half* Bb, int kiter, int tid)
{
    const int k0 = kiter * KC;
    #pragma unroll
    for (int i = 0; i < 3; i++) {
        int idx = tid + i * 256;
        if (i < 2) {
            int r = idx >> 2, c = idx & 3;
            CP_ASYNC16(stage + (uint32_t)(r * (RS*2) + c * 16),
                       Ab + (size_t)r * KD + k0 + c * 8);
        } else {
            int j = idx - 512;
            int r = j >> 2, c = j & 3;
            CP_ASYNC16(stage + ST_A + (uint32_t)(r * (RS*2) + c * 16),
                       Bb + (size_t)r * KD + k0 + c * 8);
        }
    }
}

// ---------------- shared GEMM mainloop, fully unrolled (32x32 warp tiles) ----------------
__device__ __forceinline__ void gemm_mainloop(uint32_t sb, const __half* Abase,
                                              const __half* Bbase, int tid,
                                              const uint32_t* aoff, const uint32_t* boff,
                                              float acc[8][4])
{
    load_stage(sb,       Abase, Bbase, 0, tid); CP_COMMIT();
    load_stage(sb + STG, Abase, Bbase, 1, tid); CP_COMMIT();

    #pragma unroll
    for (int it = 0; it < NIT; it++) {
        const int slot  = it % 3;
        const int slot2 = (it + 2) % 3;
        CP_WAIT1();
        __syncthreads();
        if (it + 2 < NIT) load_stage(sb + slot2 * STG, Abase, Bbase, it + 2, tid);
        CP_COMMIT();

        const uint32_t st = sb + slot * STG;
        #pragma unroll
        for (int ks = 0; ks < 2; ks++) {
            uint32_t a[2][4], b[2][4];
            #pragma unroll
            for (int i = 0; i < 2; i++)
                ldm_x4(a[i][0], a[i][1], a[i][2], a[i][3], st + aoff[i] + ks * 32);
            #pragma unroll
            for (int j = 0; j < 2; j++)
                ldm_x4(b[j][0], b[j][1], b[j][2], b[j][3], st + boff[j] + ks * 32);
            #pragma unroll
            for (int i = 0; i < 2; i++) {
                #pragma unroll
                for (int j = 0; j < 2; j++) {
                    mma16816(acc[i*4 + 2*j][0], acc[i*4 + 2*j][1], acc[i*4 + 2*j][2], acc[i*4 + 2*j][3],
                             a[i][0], a[i][1], a[i][2], a[i][3], b[j][0], b[j][2]);
                    mma16816(acc[i*4 + 2*j+1][0], acc[i*4 + 2*j+1][1], acc[i*4 + 2*j+1][2], acc[i*4 + 2*j+1][3],
                             a[i][0], a[i][1], a[i][2], a[i][3], b[j][1], b[j][3]);
                }
            }
        }
    }
}

// ---------------- fused QKV GEMM: 128x64, grid (48, 64), fp16 outputs ----------------
__global__ void __launch_bounds__(256, 3)
gemm_qkv(const __half* __restrict__ Aq, const __half* __restrict__ Wall,
         const float* __restrict__ bq, const float* __restrict__ bk, const float* __restrict__ bv,
         __half* __restrict__ Qp, __half* __restrict__ Kp, __half* __restrict__ Vp)
{
    extern __shared__ __align__(128) char smem[];
    const uint32_t sb = smem_u32(smem);
    const int tid = threadIdx.x;
    const int wid = tid >> 5, lane = tid & 31;
    const int wm = wid >> 1, wn = wid & 1;
    const int bm = blockIdx.y * TILE_M;
    const int bn = blockIdx.x * TILE_N;            // 0..3071

    const __half* Abase = Aq + (size_t)bm * KD;
    const __half* Bbase = Wall + (size_t)bn * KD;

    const int lr = lane & 15, lc = lane >> 4;
    uint32_t aoff[2], boff[2];
    #pragma unroll
    for (int i = 0; i < 2; i++)
        aoff[i] = (uint32_t)(((wm * 32 + i * 16 + lr) * RS + lc * 8) * 2);
    #pragma unroll
    for (int j = 0; j < 2; j++)
        boff[j] = (uint32_t)(ST_A + ((wn * 32 + j * 16 + lr) * RS + lc * 8) * 2);

    float acc[8][4];
    #pragma unroll
    for (int t = 0; t < 8; t++)
        #pragma unroll
        for (int q = 0; q < 4; q++) acc[t][q] = 0.f;

    gemm_mainloop(sb, Abase, Bbase, tid, aoff, boff, acc);

    const int sel = bn >> 10;
    const float* bias = (sel == 0) ? bq : (sel == 1) ? bk : bv;
    __half* C = (sel == 0) ? Qp : (sel == 1) ? Kp : Vp;
    const int cw = bn & 1023;

    const int g = lane >> 2, t4 = (lane & 3) * 2;
    #pragma unroll
    for (int i = 0; i < 2; i++) {
        #pragma unroll
        for (int j = 0; j < 4; j++) {
            const int col = cw + wn * 32 + j * 8 + t4;
            const float bx = bias[col], by = bias[col + 1];
            #pragma unroll
            for (int h = 0; h < 2; h++) {
                const size_t row = (size_t)(bm + wm * 32 + i * 16 + g + h * 8);
                half_store(C, row, col, acc[i*4 + j][h*2 + 0] + bx, acc[i*4 + j][h*2 + 1] + by);
            }
        }
    }
}

// ---------------- FF GEMM: 128x64 tiles, grid (16, 64), 3 CTAs/SM ----------------
// EPI 1 = +bias+GELU -> fp16 C2; EPI 2 = +bias + fp16 residual -> fp32 C
template<int EPI>
__global__ void __launch_bounds__(256, 3)
gemm_ff(const __half* __restrict__ Aq, const __half* __restrict__ Bq,
        const float* __restrict__ bias, const __half* __restrict__ Rres,
        float* __restrict__ C, __half* __restrict__ C2)
{
    extern __shared__ __align__(128) char smem[];
    const uint32_t sb = smem_u32(smem);
    const int tid = threadIdx.x;
    const int wid = tid >> 5, lane = tid & 31;
    const int wm = wid >> 1, wn = wid & 1;
    const int bm = blockIdx.y * TILE_M;
    const int bn = blockIdx.x * TILE_N;

    const __half* Abase = Aq + (size_t)bm * KD;
    const __half* Bbase = Bq + (size_t)bn * KD;

    const int lr = lane & 15, lc = lane >> 4;
    uint32_t aoff[2], boff[2];
    #pragma unroll
    for (int i = 0; i < 2; i++)
        aoff[i] = (uint32_t)(((wm * 32 + i * 16 + lr) * RS + lc * 8) * 2);
    #pragma unroll
    for (int j = 0; j < 2; j++)
        boff[j] = (uint32_t)(ST_A + ((wn * 32 + j * 16 + lr) * RS + lc * 8) * 2);

    float acc[8][4];
    #pragma unroll
    for (int t = 0; t < 8; t++)
        #pragma unroll
        for (int q = 0; q < 4; q++) acc[t][q] = 0.f;

    gemm_mainloop(sb, Abase, Bbase, tid, aoff, boff, acc);

    const int g = lane >> 2, t4 = (lane & 3) * 2;
    #pragma unroll
    for (int i = 0; i < 2; i++) {
        #pragma unroll
        for (int j = 0; j < 4; j++) {
            const int col = bn + wn * 32 + j * 8 + t4;
            const float bx = bias[col], by = bias[col + 1];
            #pragma unroll
            for (int h = 0; h < 2; h++) {
                const size_t row = (size_t)(bm + wm * 32 + i * 16 + g + h * 8);
                float vx = acc[i*4 + j][h*2 + 0] + bx;
                float vy = acc[i*4 + j][h*2 + 1] + by;
                if (EPI == 1) {
                    vx = gelu_exact(vx); vy = gelu_exact(vy);
                    half_store(C2, row, col, vx, vy);
                } else {
                    const __half2 rv = *(const __half2*)&Rres[row * KD + col];
                    const float2 rf = __half22float2(rv);
                    *(float2*)&C[row * ND + col] = make_float2(vx + rf.x, vy + rf.y);
                }
            }
        }
    }
}

// ---------------- fused attention: 128 threads, fp16 in, fp16 y out only ----------------
__global__ void __launch_bounds__(128, 8)
attn_fused(const __half* __restrict__ Q, const __half* __restrict__ K,
           const __half* __restrict__ V, const float* __restrict__ lp,
           const float* __restrict__ g2, const float* __restrict__ g3,
           __half* __restrict__ yh)
{
    __shared__ float sQ[1024], sK[1024], sV[1024];
    __shared__ float skv[64 * 64];
    __shared__ float sS[16];
    __shared__ float sp[4];
    __shared__ float sscale;
    float* sA = sK;                               // sK dead after kv-loop
    int pos = blockIdx.x, tid = threadIdx.x;      // 128 threads
    size_t base = (size_t)pos * 1024;

    {   // load 8 halves (one uint4) per tensor per thread, convert + elu
        const uint4 qv = ((const uint4*)(Q + base))[tid];
        const uint4 kv = ((const uint4*)(K + base))[tid];
        const uint4 vv = ((const uint4*)(V + base))[tid];
        const __half2* qh = (const __half2*)&qv;
        const __half2* kh = (const __half2*)&kv;
        const __half2* vh = (const __half2*)&vv;
        float q8[8], k8[8], v8[8];
        #pragma unroll
        for (int p = 0; p < 4; p++) {
            float2 fq = __half22float2(qh[p]);
            float2 fk = __half22float2(kh[p]);
            float2 fv = __half22float2(vh[p]);
            q8[p*2+0] = (fq.x > 0.f) ? fq.x : expm1f(fq.x);
            q8[p*2+1] = (fq.y > 0.f) ? fq.y : expm1f(fq.y);
            k8[p*2+0] = (fk.x > 0.f) ? fk.x : expm1f(fk.x);
            k8[p*2+1] = (fk.y > 0.f) ? fk.y : expm1f(fk.y);
            v8[p*2+0] = fv.x; v8[p*2+1] = fv.y;
        }
        *(float4*)&sQ[tid*8]     = *(float4*)&q8[0];
        *(float4*)&sQ[tid*8 + 4] = *(float4*)&q8[4];
        *(float4*)&sK[tid*8]     = *(float4*)&k8[0];
        *(float4*)&sK[tid*8 + 4] = *(float4*)&k8[4];
        *(float4*)&sV[tid*8]     = *(float4*)&v8[0];
        *(float4*)&sV[tid*8 + 4] = *(float4*)&v8[4];
    }
    __syncthreads();

    // kv[d][e] = SCALE * sum_h phi(K)[h,d] * V[h,e]
    {
        const int d0 = (tid >> 4) * 4;
        const int d1 = d0 + 32;
        const int e4 = (tid & 15) * 4;
        float4 a0 = make_float4(0.f,0.f,0.f,0.f), a1 = a0, a2 = a0, a3 = a0;
        float4 b0 = a0, b1 = a0, b2 = a0, b3 = a0;
        #pragma unroll
        for (int h = 0; h < 16; h++) {
            float4 vv = *(const float4*)&sV[h * 64 + e4];
            float4 k0 = *(const float4*)&sK[h * 64 + d0];
            float4 k1 = *(const float4*)&sK[h * 64 + d1];
            a0.x += k0.x * vv.x; a0.y += k0.x * vv.y; a0.z += k0.x * vv.z; a0.w += k0.x * vv.w;
            a1.x += k0.y * vv.x; a1.y += k0.y * vv.y; a1.z += k0.y * vv.z; a1.w += k0.y * vv.w;
            a2.x += k0.z * vv.x; a2.y += k0.z * vv.y; a2.z += k0.z * vv.z; a2.w += k0.z * vv.w;
            a3.x += k0.w * vv.x; a3.y += k0.w * vv.y; a3.z += k0.w * vv.z; a3.w += k0.w * vv.w;
            b0.x += k1.x * vv.x; b0.y += k1.x * vv.y; b0.z += k1.x * vv.z; b0.w += k1.x * vv.w;
            b1.x += k1.y * vv.x; b1.y += k1.y * vv.y; b1.z += k1.y * vv.z; b1.w += k1.y * vv.w;
            b2.x += k1.z * vv.x; b2.y += k1.z * vv.y; b2.z += k1.z * vv.z; b2.w += k1.z * vv.w;
            b3.x += k1.w * vv.x; b3.y += k1.w * vv.y; b3.z += k1.w * vv.z; b3.w += k1.w * vv.w;
        }
        #define SCL(t) t.x *= SCALE_ATT; t.y *= SCALE_ATT; t.z *= SCALE_ATT; t.w *= SCALE_ATT
        SCL(a0); SCL(a1); SCL(a2); SCL(a3); SCL(b0); SCL(b1); SCL(b2); SCL(b3);
        #undef SCL
        *(float4*)&skv[(d0+0) * 64 + e4] = a0;
        *(float4*)&skv[(d0+1) * 64 + e4] = a1;
        *(float4*)&skv[(d0+2) * 64 + e4] = a2;
        *(float4*)&skv[(d0+3) * 64 + e4] = a3;
        *(float4*)&skv[(d1+0) * 64 + e4] = b0;
        *(float4*)&skv[(d1+1) * 64 + e4] = b1;
        *(float4*)&skv[(d1+2) * 64 + e4] = b2;
        *(float4*)&skv[(d1+3) * 64 + e4] = b3;
    }
    __syncthreads();

    float lam = expf(lp[0] * lp[1]) - expf(lp[2] * lp[3]) + LAM_INIT;

    // a[h][e4]: heads hA and hA+8 per thread (share skv loads)
    {
        const int hA = tid >> 4;
        const int e4 = (tid & 15) * 4;
        float4 s1a = make_float4(0.f,0.f,0.f,0.f), s2a = s1a;
        float4 s1b = s1a, s2b = s1a;
        #pragma unroll
        for (int dd = 0; dd < 8; dd++) {
            float4 q1a = *(const float4*)&sQ[hA * 64 + dd * 4];
            float4 q2a = *(const float4*)&sQ[hA * 64 + 32 + dd * 4];
            float4 q1b = *(const float4*)&sQ[(hA + 8) * 64 + dd * 4];
            float4 q2b = *(const float4*)&sQ[(hA + 8) * 64 + 32 + dd * 4];
            float qa1[4] = {q1a.x, q1a.y, q1a.z, q1a.w};
            float qa2[4] = {q2a.x, q2a.y, q2a.z, q2a.w};
            float qb1[4] = {q1b.x, q1b.y, q1b.z, q1b.w};
            float qb2[4] = {q2b.x, q2b.y, q2b.z, q2b.w};
            #pragma unroll
            for (int j = 0; j < 4; j++) {
                int d = dd * 4 + j;
                float4 f1 = *(const float4*)&skv[d * 64 + e4];
                float4 f2 = *(const float4*)&skv[(32 + d) * 64 + e4];
                s1a.x += qa1[j] * f1.x; s1a.y += qa1[j] * f1.y;
                s1a.z += qa1[j] * f1.z; s1a.w += qa1[j] * f1.w;
                s2a.x += qa2[j] * f2.x; s2a.y += qa2[j] * f2.y;
                s2a.z += qa2[j] * f2.z; s2a.w += qa2[j] * f2.w;
                s1b.x += qb1[j] * f1.x; s1b.y += qb1[j] * f1.y;
                s1b.z += qb1[j] * f1.z; s1b.w += qb1[j] * f1.w;
                s2b.x += qb2[j] * f2.x; s2b.y += qb2[j] * f2.y;
                s2b.z += qb2[j] * f2.z; s2b.w += qb2[j] * f2.w;
            }
        }
        float4 ra, rb;
        ra.x = s1a.x - lam * s2a.x; ra.y = s1a.y - lam * s2a.y;
        ra.z = s1a.z - lam * s2a.z; ra.w = s1a.w - lam * s2a.w;
        rb.x = s1b.x - lam * s2b.x; rb.y = s1b.y - lam * s2b.y;
        rb.z = s1b.z - lam * s2b.z; rb.w = s1b.w - lam * s2b.w;
        *(float4*)&sA[hA * 64 + e4]       = ra;
        *(float4*)&sA[(hA + 8) * 64 + e4] = rb;
    }
    __syncthreads();

    if (tid < 16) {
        float ss = 0.f;
        #pragma unroll
        for (int e = 0; e < 16; e++) {
            float4 v = *(const float4*)&sA[tid * 64 + e * 4];
            ss += v.x*v.x + v.y*v.y + v.z*v.z + v.w*v.w;
        }
        sS[tid] = rsqrtf(ss * (1.0f/64.0f) + EPSF) * ONE_MINUS_LAM_INIT;
    }
    __syncthreads();

    const int i0 = tid * 8;
    const int hh = i0 >> 6;
    float v0[8];
    float ss = 0.f;
    {
        float s = sS[hh];
        #pragma unroll
        for (int half = 0; half < 2; half++) {
            float4 av = *(const float4*)&sA[i0 + half * 4];
            float4 gg = *(const float4*)&g2[(i0 + half * 4) & 63];
            v0[half*4+0] = av.x * s * gg.x; v0[half*4+1] = av.y * s * gg.y;
            v0[half*4+2] = av.z * s * gg.z; v0[half*4+3] = av.w * s * gg.w;
        }
        #pragma unroll
        for (int j = 0; j < 8; j++) ss += v0[j] * v0[j];
    }
    #pragma unroll
    for (int o = 16; o > 0; o >>= 1) ss += __shfl_xor_sync(0xffffffffu, ss, o);
    if ((tid & 31) == 0) sp[tid >> 5] = ss;
    __syncthreads();
    if (tid == 0) {
        float s = sp[0] + sp[1] + sp[2] + sp[3];
        sscale = rsqrtf(s * (1.0f/1024.0f) + EPSF);
    }
    __syncthreads();
    const float sc = sscale;
    #pragma unroll
    for (int half = 0; half < 2; half++) {
        float4 g3v = ((const float4*)g3)[tid * 2 + half];
        float y0 = v0[half*4+0] * sc * g3v.x + v0[half*4+0];
        float y1 = v0[half*4+1] * sc * g3v.y + v0[half*4+1];
        float y2 = v0[half*4+2] * sc * g3v.z + v0[half*4+2];
        float y3 = v0[half*4+3] * sc * g3v.w + v0[half*4+3];
        half_store(yh, (size_t)pos, i0 + half * 4,     y0, y1);
        half_store(yh, (size_t)pos, i0 + half * 4 + 2, y2, y3);
    }
}

// ============================================================
extern "C" void kernel_launch(void* const* d_in, const int* in_sizes, int n_in,
                              void* d_out, int out_size)
{
    const float* x   = (const float*)d_in[0];
    const float* Wq  = (const float*)d_in[1];
    const float* bq  = (const float*)d_in[2];
    const float* Wk  = (const float*)d_in[3];
    const float* bk  = (const float*)d_in[4];
    const float* Wv  = (const float*)d_in[5];
    const float* bv  = (const float*)d_in[6];
    const float* lp  = (const float*)d_in[7];
    const float* g1  = (const float*)d_in[8];
    const float* g2  = (const float*)d_in[9];
    const float* g3  = (const float*)d_in[10];
    const float* Wf1 = (const float*)d_in[11];
    const float* bf1 = (const float*)d_in[12];
    const float* Wf2 = (const float*)d_in[13];
    const float* bf2 = (const float*)d_in[14];
    float* out = (float*)d_out;

    __half *Qh, *Kh, *Vh, *A1, *A2, *Wall;
    cudaGetSymbolAddress((void**)&Qh, g_Qh);
    cudaGetSymbolAddress((void**)&Kh, g_Kh);
    cudaGetSymbolAddress((void**)&Vh, g_Vh);
    cudaGetSymbolAddress((void**)&A1, g_A1);
    cudaGetSymbolAddress((void**)&A2, g_A2);
    cudaGetSymbolAddress((void**)&Wall, g_W);

    cudaFuncSetAttribute(gemm_qkv,   cudaFuncAttributeMaxDynamicSharedMemorySize, SMEM_DYN);
    cudaFuncSetAttribute(gemm_ff<1>, cudaFuncAttributeMaxDynamicSharedMemorySize, SMEM_DYN);
    cudaFuncSetAttribute(gemm_ff<2>, cudaFuncAttributeMaxDynamicSharedMemorySize, SMEM_DYN);

    prep_k<<<M_TOT + 1280, 256>>>(x, g1, A1, Wq, Wk, Wv, Wf1, Wf2, Wall);

    gemm_qkv<<<dim3(48, 64), 256, SMEM_DYN>>>(A1, Wall, bq, bk, bv, Qh, Kh, Vh);

    attn_fused<<<M_TOT, 128>>>(Qh, Kh, Vh, lp, g2, g3, A1);    // A1 <- y (fp16)

    gemm_ff<1><<<dim3(16, 64), 256, SMEM_DYN>>>(A1, Wall + 3*WMAT, bf1, nullptr, nullptr, A2);
    gemm_ff<2><<<dim3(16, 64), 256, SMEM_DYN>>>(A2, Wall + 4*WMAT, bf2, A1, out, nullptr);
}